// round 14
// baseline (speedup 1.0000x reference)
#include <cuda_runtime.h>
#include <cuda_bf16.h>

// Problem constants
#define B_   8
#define S1_  512
#define S2_  512
#define HID_ 128
#define HD_  128
#define TSPLIT 8

// ---------------- scratch (static device memory; no allocations) -------------
__device__ float g_qp  [B_ * S1_ * HID_];                 // 2 MB
__device__ float g_kp  [B_ * S2_ * HID_];                 // 2 MB
__device__ float g_a   [B_ * S1_];                        // 0.5*qp.W2 + b2
__device__ float g_c   [B_ * S2_];                        // 0.5*kp.W2
__device__ int   g_slist[B_ * S1_];                       // compacted active s ids
__device__ int   g_tlist[B_ * S2_];                       // compacted active t ids
__device__ int   g_ns[B_], g_nt[B_];
__device__ float g_pout[TSPLIT * B_ * S1_ * HD_];         // 16 MB value partials
__device__ float g_pden[TSPLIT * B_ * S1_];               // denominator partials

// ---------------- packed f32x2 helpers (Blackwell-only PTX) ------------------
__device__ __forceinline__ unsigned long long f32x2_add(unsigned long long a,
                                                        unsigned long long b) {
    unsigned long long r;
    asm("add.rn.f32x2 %0, %1, %2;" : "=l"(r) : "l"(a), "l"(b));
    return r;
}
__device__ __forceinline__ unsigned long long f32x2_fma(unsigned long long a,
                                                        unsigned long long b,
                                                        unsigned long long c) {
    unsigned long long r;
    asm("fma.rn.f32x2 %0, %1, %2, %3;" : "=l"(r) : "l"(a), "l"(b), "l"(c));
    return r;
}
__device__ __forceinline__ unsigned long long f32x2_pack(float lo, float hi) {
    unsigned long long r;
    asm("mov.b64 %0, {%1, %2};" : "=l"(r) : "f"(lo), "f"(hi));
    return r;
}
__device__ __forceinline__ void f32x2_unpack(unsigned long long a, float& lo, float& hi) {
    asm("mov.b64 {%0, %1}, %2;" : "=f"(lo), "=f"(hi) : "l"(a));
}
__device__ __forceinline__ float bfly_step(float keep, float send, int off) {
    return keep + __shfl_xor_sync(0xffffffffu, send, off);
}

// ================= Kernel 0: compact active s / t index lists ================
// One block per batch, 512 threads. Deterministic ballot+scan compaction.
// Lists are padded to full length with the FIRST ACTIVE index (valid data).
__global__ __launch_bounds__(512) void compact_kernel(
    const int* __restrict__ q_mask, const int* __restrict__ k_mask)
{
    __shared__ int wcnt[16], woff[16];
    __shared__ int total_sh;
    const int b = blockIdx.x, tid = threadIdx.x;
    const int lane = tid & 31, wid = tid >> 5;

    // ---- t side (k_mask) ----
    int m = k_mask[b * S2_ + tid] != 0;
    unsigned bal = __ballot_sync(0xffffffffu, m);
    if (lane == 0) wcnt[wid] = __popc(bal);
    __syncthreads();
    if (tid == 0) {
        int acc = 0;
        for (int i = 0; i < 16; i++) { woff[i] = acc; acc += wcnt[i]; }
        total_sh = acc;
    }
    __syncthreads();
    int pos = woff[wid] + __popc(bal & ((1u << lane) - 1));
    if (m) g_tlist[b * S2_ + pos] = tid;
    int ntv = total_sh;
    if (tid == 0) g_nt[b] = ntv;
    __syncthreads();
    int pad_t = (ntv > 0) ? g_tlist[b * S2_] : 0;
    for (int j = ntv + tid; j < S2_; j += 512) g_tlist[b * S2_ + j] = pad_t;
    __syncthreads();

    // ---- s side (q_mask) ----
    m = q_mask[b * S1_ + tid] != 0;
    bal = __ballot_sync(0xffffffffu, m);
    if (lane == 0) wcnt[wid] = __popc(bal);
    __syncthreads();
    if (tid == 0) {
        int acc = 0;
        for (int i = 0; i < 16; i++) { woff[i] = acc; acc += wcnt[i]; }
        total_sh = acc;
    }
    __syncthreads();
    pos = woff[wid] + __popc(bal & ((1u << lane) - 1));
    if (m) g_slist[b * S1_ + pos] = tid;
    int nsv = total_sh;
    if (tid == 0) g_ns[b] = nsv;
    __syncthreads();
    int pad_s = (nsv > 0) ? g_slist[b * S1_] : 0;
    for (int j = nsv + tid; j < S1_; j += 512) g_slist[b * S1_ + j] = pad_s;
}

// ================= Kernel 1: projections (ACTIVE rows only) ==================
// qp[r][h] = sum_d Q[r][d]*W1[h][d] + b1[h];  kp[r][h] = sum_d K[r][d]*W1[h][128+d]
// Epilogue: a[r] = 0.5*qp.W2 + b2 ; c[r] = 0.5*kp.W2  (rows all active)
// grid (B*16, 2), block 256; block = 32 compacted rows of one batch; tiles
// beyond the active count exit immediately (~2x less work).
__global__ __launch_bounds__(256) void proj_kernel(
    const float* __restrict__ query, const float* __restrict__ key,
    const float* __restrict__ W1, const float* __restrict__ b1,
    const float* __restrict__ W2, const float* __restrict__ b2)
{
    __shared__ float xs[32][33];
    __shared__ float ws[32][132];
    __shared__ int   ids[32];

    const int tid = threadIdx.x;
    const int tx = tid & 31;
    const int ty = tid >> 5;
    const int b = blockIdx.x >> 4;
    const int tile = blockIdx.x & 15;
    const int part = blockIdx.y;

    const int n = part ? g_nt[b] : g_ns[b];
    const int R0 = tile * 32;
    if (R0 >= n) return;

    const int* list = (part ? g_tlist : g_slist) + b * 512;
    if (tid < 32) ids[tid] = list[R0 + tid];       // padded => always valid
    __syncthreads();

    const float* X = part ? key : query;
    float* out = part ? g_kp : g_qp;
    const int woff = part * 128;

    unsigned long long acc2[4][2];
    if (part == 0) {
        float4 bv = *reinterpret_cast<const float4*>(b1 + tx * 4);
        unsigned long long b01 = f32x2_pack(bv.x, bv.y);
        unsigned long long b23 = f32x2_pack(bv.z, bv.w);
        #pragma unroll
        for (int i = 0; i < 4; i++) { acc2[i][0] = b01; acc2[i][1] = b23; }
    } else {
        #pragma unroll
        for (int i = 0; i < 4; i++) { acc2[i][0] = 0ULL; acc2[i][1] = 0ULL; }
    }

    const int xr = tid >> 3, xk = (tid & 7) * 4;
    const size_t xrow = (size_t)(b * 512 + ids[xr]) * 128;

    float4 xreg = *reinterpret_cast<const float4*>(X + xrow + xk);
    float4 wreg[4];
    #pragma unroll
    for (int j = 0; j < 4; j++) {
        int idx = tid + j * 256;
        int h = idx >> 3, k4 = (idx & 7) * 4;
        wreg[j] = *reinterpret_cast<const float4*>(W1 + (size_t)h * 256 + woff + k4);
    }

    for (int kc = 0; kc < 4; kc++) {
        xs[xr][xk + 0] = xreg.x; xs[xr][xk + 1] = xreg.y;
        xs[xr][xk + 2] = xreg.z; xs[xr][xk + 3] = xreg.w;
        #pragma unroll
        for (int j = 0; j < 4; j++) {
            int idx = tid + j * 256;
            int h = idx >> 3, k4 = (idx & 7) * 4;
            ws[k4 + 0][h] = wreg[j].x; ws[k4 + 1][h] = wreg[j].y;
            ws[k4 + 2][h] = wreg[j].z; ws[k4 + 3][h] = wreg[j].w;
        }
        __syncthreads();

        if (kc < 3) {
            xreg = *reinterpret_cast<const float4*>(X + xrow + (kc + 1) * 32 + xk);
            #pragma unroll
            for (int j = 0; j < 4; j++) {
                int idx = tid + j * 256;
                int h = idx >> 3, k4 = (idx & 7) * 4;
                wreg[j] = *reinterpret_cast<const float4*>(
                    W1 + (size_t)h * 256 + woff + (kc + 1) * 32 + k4);
            }
        }

        #pragma unroll 8
        for (int k = 0; k < 32; k++) {
            ulonglong2 wv2 = *reinterpret_cast<const ulonglong2*>(&ws[k][tx * 4]);
            #pragma unroll
            for (int i = 0; i < 4; i++) {
                float xv = xs[ty + 8 * i][k];
                unsigned long long xx = f32x2_pack(xv, xv);
                acc2[i][0] = f32x2_fma(wv2.x, xx, acc2[i][0]);
                acc2[i][1] = f32x2_fma(wv2.y, xx, acc2[i][1]);
            }
        }
        __syncthreads();
    }

    float4 accf[4];
    #pragma unroll
    for (int i = 0; i < 4; i++) {
        f32x2_unpack(acc2[i][0], accf[i].x, accf[i].y);
        f32x2_unpack(acc2[i][1], accf[i].z, accf[i].w);
        int r = b * 512 + ids[ty + 8 * i];       // duplicates write identical data
        *reinterpret_cast<float4*>(out + (size_t)r * 128 + tx * 4) = accf[i];
    }

    float4 w2v = *reinterpret_cast<const float4*>(W2 + tx * 4);
    #pragma unroll
    for (int i = 0; i < 4; i++) {
        float ps = accf[i].x * w2v.x + accf[i].y * w2v.y
                 + accf[i].z * w2v.z + accf[i].w * w2v.w;
        #pragma unroll
        for (int off = 16; off >= 1; off >>= 1)
            ps += __shfl_xor_sync(0xffffffffu, ps, off);
        if (tx == 0) {
            int r = b * 512 + ids[ty + 8 * i];
            if (part == 0) g_a[r] = 0.5f * ps + b2[0];
            else           g_c[r] = 0.5f * ps;
        }
    }
}

// ================= Kernel 2: fused scoring + exp + value accum (compacted) ===
// s[b,s,t] = a_s + c_t + sum_h 0.5*W2_h*|qp_h + kp_h|   (relu identity)
// grid (S1/64, TSPLIT, B), block 256; tz block handles chunks c = tz, tz+8, ...
__global__ __launch_bounds__(256, 2) void attn_kernel(
    const float* __restrict__ value, const float* __restrict__ W2)
{
    __shared__ float kp_s[32 * 128];    // permuted: chunk (hc, ib) at slot ib*8+hc
    __shared__ float v_s [32 * 128];
    __shared__ float c_s [32];
    __shared__ int   s_ids[64];

    const int tid = threadIdx.x;
    const int warp = tid >> 5, lane = tid & 31;
    const int s_local = lane >> 3, hc = lane & 7;
    const int stile = blockIdx.x, tz = blockIdx.y, b = blockIdx.z;

    const int ns = g_ns[b], nt = g_nt[b];
    if (stile * 64 >= ns) return;

    if (tid < 64) s_ids[tid] = g_slist[b * S1_ + stile * 64 + tid];
    __syncthreads();

    const int iiA = warp * 8 + s_local;
    const bool vA = stile * 64 + iiA < ns;
    const bool vB = stile * 64 + iiA + 4 < ns;
    const int sA = s_ids[iiA];
    const int sB = s_ids[iiA + 4];
    const int rowA = b * S1_ + sA;
    const int rowB = b * S1_ + sB;

    unsigned long long qpA2[8], qpB2[8], w2p[8];
    {
        const float4* qrowA = reinterpret_cast<const float4*>(
            g_qp + (size_t)rowA * HID_ + hc * 16);
        const float4* qrowB = reinterpret_cast<const float4*>(
            g_qp + (size_t)rowB * HID_ + hc * 16);
        #pragma unroll
        for (int i = 0; i < 4; i++) {
            float4 qa = qrowA[i];
            qpA2[2 * i]     = f32x2_pack(qa.x, qa.y);
            qpA2[2 * i + 1] = f32x2_pack(qa.z, qa.w);
            float4 qb = qrowB[i];
            qpB2[2 * i]     = f32x2_pack(qb.x, qb.y);
            qpB2[2 * i + 1] = f32x2_pack(qb.z, qb.w);
            float4 w = *reinterpret_cast<const float4*>(W2 + hc * 16 + i * 4);
            w2p[2 * i]     = f32x2_pack(0.5f * w.x, 0.5f * w.y);
            w2p[2 * i + 1] = f32x2_pack(0.5f * w.z, 0.5f * w.w);
        }
    }
    const float aA = g_a[rowA];
    const float aB = g_a[rowB];

    unsigned long long vaccA[8], vaccB[8];
    #pragma unroll
    for (int i = 0; i < 8; i++) { vaccA[i] = 0ULL; vaccB[i] = 0ULL; }
    float denA = 0.f, denB = 0.f;

    const unsigned long long ABS2 = 0x7FFFFFFF7FFFFFFFULL;
    const int bit0 = hc & 1, bit1 = (hc >> 1) & 1, bit2 = (hc >> 2) & 1;
    const int bcast = lane & 24;
    const int* tlist = g_tlist + b * S2_;

    for (int c = tz; c * 32 < nt; c += TSPLIT) {
        const int jb = c * 32;
        __syncthreads();
        #pragma unroll
        for (int j = 0; j < 4; j++) {
            int idx = tid + j * 256;            // 0..1023 float4s
            int tt = idx >> 5, l = idx & 31;
            int t = tlist[jb + tt];             // padded with first active t
            int h4 = ((l & 7) << 2) | (l >> 3); // inverse of slot permutation
            const float4* krow = reinterpret_cast<const float4*>(
                g_kp + (size_t)(b * S2_ + t) * HID_);
            const float4* vrow = reinterpret_cast<const float4*>(
                value + (size_t)(b * S2_ + t) * HD_);
            reinterpret_cast<float4*>(kp_s)[tt * 32 + l] = krow[h4];
            reinterpret_cast<float4*>(v_s )[tt * 32 + l] = vrow[h4];
        }
        if (tid < 32) {
            int j = jb + tid;
            c_s[tid] = (j < nt) ? g_c[b * S2_ + tlist[j]] : -1e30f;
        }
        __syncthreads();

        #pragma unroll 1
        for (int g = 0; g < 4; g++) {
            float rA[4], rB[4];
            #pragma unroll
            for (int k = 0; k < 4; k++) {
                float m0A, m0B, m1A, m1B;
                #pragma unroll
                for (int half = 0; half < 2; half++) {
                    const float* kprow = kp_s + (g * 8 + 2 * k + half) * 128;
                    unsigned long long a0 = 0ULL, a1 = 0ULL, b0 = 0ULL, b1 = 0ULL;
                    #pragma unroll
                    for (int ib = 0; ib < 4; ib++) {
                        ulonglong2 kv = *reinterpret_cast<const ulonglong2*>(
                            kprow + ib * 32 + hc * 4);
                        unsigned long long xA01 = f32x2_add(qpA2[2 * ib],     kv.x) & ABS2;
                        unsigned long long xA23 = f32x2_add(qpA2[2 * ib + 1], kv.y) & ABS2;
                        unsigned long long xB01 = f32x2_add(qpB2[2 * ib],     kv.x) & ABS2;
                        unsigned long long xB23 = f32x2_add(qpB2[2 * ib + 1], kv.y) & ABS2;
                        a0 = f32x2_fma(xA01, w2p[2 * ib],     a0);
                        a1 = f32x2_fma(xA23, w2p[2 * ib + 1], a1);
                        b0 = f32x2_fma(xB01, w2p[2 * ib],     b0);
                        b1 = f32x2_fma(xB23, w2p[2 * ib + 1], b1);
                    }
                    float la, ha, lb, hb;
                    f32x2_unpack(f32x2_add(a0, a1), la, ha);
                    f32x2_unpack(f32x2_add(b0, b1), lb, hb);
                    if (half == 0) { m0A = la + ha; m0B = lb + hb; }
                    else           { m1A = la + ha; m1B = lb + hb; }
                }
                rA[k] = bfly_step(bit0 ? m1A : m0A, bit0 ? m0A : m1A, 1);
                rB[k] = bfly_step(bit0 ? m1B : m0B, bit0 ? m0B : m1B, 1);
            }
            float sA2[2], sB2[2];
            #pragma unroll
            for (int k = 0; k < 2; k++) {
                sA2[k] = bfly_step(bit1 ? rA[2 * k + 1] : rA[2 * k],
                                   bit1 ? rA[2 * k] : rA[2 * k + 1], 2);
                sB2[k] = bfly_step(bit1 ? rB[2 * k + 1] : rB[2 * k],
                                   bit1 ? rB[2 * k] : rB[2 * k + 1], 2);
            }
            float scA = bfly_step(bit2 ? sA2[1] : sA2[0],
                                  bit2 ? sA2[0] : sA2[1], 4);
            float scB = bfly_step(bit2 ? sB2[1] : sB2[0],
                                  bit2 ? sB2[0] : sB2[1], 4);

            float ct = c_s[g * 8 + hc];
            float pA = __expf(scA + aA + ct);   // ct = -1e30 on padding => p = 0
            float pB = __expf(scB + aB + ct);
            denA += pA;
            denB += pB;

            #pragma unroll
            for (int j = 0; j < 8; j++) {
                float pAj = __shfl_sync(0xffffffffu, pA, bcast + j);
                float pBj = __shfl_sync(0xffffffffu, pB, bcast + j);
                unsigned long long pA2 = f32x2_pack(pAj, pAj);
                unsigned long long pB2 = f32x2_pack(pBj, pBj);
                const float* vrow2 = v_s + (g * 8 + j) * 128;
                #pragma unroll
                for (int m = 0; m < 4; m++) {
                    ulonglong2 vv = *reinterpret_cast<const ulonglong2*>(
                        vrow2 + m * 32 + hc * 4);
                    vaccA[2 * m]     = f32x2_fma(vv.x, pA2, vaccA[2 * m]);
                    vaccA[2 * m + 1] = f32x2_fma(vv.y, pA2, vaccA[2 * m + 1]);
                    vaccB[2 * m]     = f32x2_fma(vv.x, pB2, vaccB[2 * m]);
                    vaccB[2 * m + 1] = f32x2_fma(vv.y, pB2, vaccB[2 * m + 1]);
                }
            }
        }
    }

    #pragma unroll
    for (int off = 1; off <= 4; off <<= 1) {
        denA += __shfl_xor_sync(0xffffffffu, denA, off);
        denB += __shfl_xor_sync(0xffffffffu, denB, off);
    }

    if (vA) {
        float* outA = g_pout + ((size_t)(tz * B_ + b) * S1_ + sA) * HD_ + hc * 16;
        #pragma unroll
        for (int m = 0; m < 4; m++) {
            float x0, x1, x2, x3;
            f32x2_unpack(vaccA[2 * m],     x0, x1);
            f32x2_unpack(vaccA[2 * m + 1], x2, x3);
            *reinterpret_cast<float4*>(outA + m * 4) = make_float4(x0, x1, x2, x3);
        }
        if (hc == 0) g_pden[(size_t)(tz * B_ + b) * S1_ + sA] = denA;
    }
    if (vB) {
        float* outB = g_pout + ((size_t)(tz * B_ + b) * S1_ + sB) * HD_ + hc * 16;
        #pragma unroll
        for (int m = 0; m < 4; m++) {
            float x0, x1, x2, x3;
            f32x2_unpack(vaccB[2 * m],     x0, x1);
            f32x2_unpack(vaccB[2 * m + 1], x2, x3);
            *reinterpret_cast<float4*>(outB + m * 4) = make_float4(x0, x1, x2, x3);
        }
        if (hc == 0) g_pden[(size_t)(tz * B_ + b) * S1_ + sB] = denB;
    }
}

// ================= Kernel 3: reduce partials + normalize + q_mask ============
__global__ __launch_bounds__(256) void reduce_kernel(
    const int* __restrict__ q_mask, float* __restrict__ out)
{
    int idx = blockIdx.x * 256 + threadIdx.x;   // float4 index
    if (idx >= B_ * S1_ * (HD_ / 4)) return;
    int d4 = idx & 31;
    int row = idx >> 5;                          // b*S1 + s
    if (q_mask[row] == 0) {                      // masked row: exact zero output
        reinterpret_cast<float4*>(out)[idx] = make_float4(0.f, 0.f, 0.f, 0.f);
        return;
    }
    float4 sum = make_float4(0.f, 0.f, 0.f, 0.f);
    float dsum = 0.f;
    #pragma unroll
    for (int k = 0; k < TSPLIT; k++) {
        float4 p = reinterpret_cast<const float4*>(g_pout)
                       [((size_t)k * B_ * S1_ + row) * 32 + d4];
        sum.x += p.x; sum.y += p.y; sum.z += p.z; sum.w += p.w;
        dsum += g_pden[(size_t)k * B_ * S1_ + row];
    }
    float scale = 1.0f / fmaxf(dsum, 2e-15f);
    reinterpret_cast<float4*>(out)[idx] =
        make_float4(sum.x * scale, sum.y * scale, sum.z * scale, sum.w * scale);
}

// ================= launch ====================================================
extern "C" void kernel_launch(void* const* d_in, const int* in_sizes, int n_in,
                              void* d_out, int out_size)
{
    const float* query  = (const float*)d_in[0];
    const float* key    = (const float*)d_in[1];
    const float* value  = (const float*)d_in[2];
    const int*   q_mask = (const int*)  d_in[3];
    const int*   k_mask = (const int*)  d_in[4];
    const float* W1     = (const float*)d_in[5];
    const float* b1     = (const float*)d_in[6];
    const float* W2     = (const float*)d_in[7];
    const float* b2     = (const float*)d_in[8];
    float* out = (float*)d_out;

    compact_kernel<<<B_, 512>>>(q_mask, k_mask);
    proj_kernel  <<<dim3(B_ * 16, 2), 256>>>(query, key, W1, b1, W2, b2);
    attn_kernel  <<<dim3(S1_ / 64, TSPLIT, B_), 256>>>(value, W2);
    reduce_kernel<<<(B_ * S1_ * (HD_ / 4) + 255) / 256, 256>>>(q_mask, out);
}

// round 15
// speedup vs baseline: 1.5422x; 1.5422x over previous
#include <cuda_runtime.h>
#include <cuda_bf16.h>

// Problem constants
#define B_   8
#define S1_  512
#define S2_  512
#define HID_ 128
#define HD_  128
#define TSPLIT 8

// ---------------- scratch (static device memory; no allocations) -------------
__device__ float g_qp  [B_ * S1_ * HID_];                 // 2 MB
__device__ float g_kp  [B_ * S2_ * HID_];                 // 2 MB
__device__ float g_a   [B_ * S1_];                        // 0.5*qp.W2 + b2
__device__ float g_c   [B_ * S2_];                        // 0.5*kp.W2 (or -1e30 if masked)
__device__ int   g_slist[B_ * S1_];                       // compacted active s ids
__device__ int   g_tlist[B_ * S2_];                       // compacted active t ids
__device__ int   g_ns[B_], g_nt[B_];
__device__ float g_pout[B_ * S1_ * TSPLIT * HD_];         // [row][k][d] partials
__device__ float g_pden[B_ * S1_ * TSPLIT];               // [row][k] partials

// ---------------- packed f32x2 helpers (Blackwell-only PTX) ------------------
__device__ __forceinline__ unsigned long long f32x2_add(unsigned long long a,
                                                        unsigned long long b) {
    unsigned long long r;
    asm("add.rn.f32x2 %0, %1, %2;" : "=l"(r) : "l"(a), "l"(b));
    return r;
}
__device__ __forceinline__ unsigned long long f32x2_fma(unsigned long long a,
                                                        unsigned long long b,
                                                        unsigned long long c) {
    unsigned long long r;
    asm("fma.rn.f32x2 %0, %1, %2, %3;" : "=l"(r) : "l"(a), "l"(b), "l"(c));
    return r;
}
__device__ __forceinline__ unsigned long long f32x2_pack(float lo, float hi) {
    unsigned long long r;
    asm("mov.b64 %0, {%1, %2};" : "=l"(r) : "f"(lo), "f"(hi));
    return r;
}
__device__ __forceinline__ void f32x2_unpack(unsigned long long a, float& lo, float& hi) {
    asm("mov.b64 {%0, %1}, %2;" : "=f"(lo), "=f"(hi) : "l"(a));
}
__device__ __forceinline__ float bfly_step(float keep, float send, int off) {
    return keep + __shfl_xor_sync(0xffffffffu, send, off);
}

// ================= Kernel 0: compact active s / t index lists ================
// One block per batch, 512 threads. Deterministic ballot+scan compaction.
__global__ __launch_bounds__(512) void compact_kernel(
    const int* __restrict__ q_mask, const int* __restrict__ k_mask)
{
    __shared__ int wcnt[16], woff[16];
    __shared__ int total_sh;
    const int b = blockIdx.x, tid = threadIdx.x;
    const int lane = tid & 31, wid = tid >> 5;

    // ---- t side (k_mask) ----
    int m = k_mask[b * S2_ + tid] != 0;
    unsigned bal = __ballot_sync(0xffffffffu, m);
    if (lane == 0) wcnt[wid] = __popc(bal);
    __syncthreads();
    if (tid == 0) {
        int acc = 0;
        for (int i = 0; i < 16; i++) { woff[i] = acc; acc += wcnt[i]; }
        total_sh = acc;
    }
    __syncthreads();
    int pos = woff[wid] + __popc(bal & ((1u << lane) - 1));
    if (m) g_tlist[b * S2_ + pos] = tid;
    int ntv = total_sh;
    if (tid == 0) g_nt[b] = ntv;
    for (int j = ntv + tid; j < S2_; j += 512) g_tlist[b * S2_ + j] = 0;
    __syncthreads();

    // ---- s side (q_mask) ----
    m = q_mask[b * S1_ + tid] != 0;
    bal = __ballot_sync(0xffffffffu, m);
    if (lane == 0) wcnt[wid] = __popc(bal);
    __syncthreads();
    if (tid == 0) {
        int acc = 0;
        for (int i = 0; i < 16; i++) { woff[i] = acc; acc += wcnt[i]; }
        total_sh = acc;
    }
    __syncthreads();
    pos = woff[wid] + __popc(bal & ((1u << lane) - 1));
    if (m) g_slist[b * S1_ + pos] = tid;
    int nsv = total_sh;
    if (tid == 0) g_ns[b] = nsv;
    for (int j = nsv + tid; j < S1_; j += 512) g_slist[b * S1_ + j] = 0;
}

// ================= Kernel 1: projections qp / kp + linear score terms ========
// (R4/R11 version — measured best.) grid (128, 2), block 256. ALL rows.
__global__ __launch_bounds__(256) void proj_kernel(
    const float* __restrict__ query, const float* __restrict__ key,
    const float* __restrict__ W1, const float* __restrict__ b1,
    const float* __restrict__ W2, const float* __restrict__ b2,
    const int* __restrict__ k_mask)
{
    __shared__ float xs[32][33];
    __shared__ float ws[32][132];

    const int tid = threadIdx.x;
    const int tx = tid & 31;
    const int ty = tid >> 5;
    const int R0 = blockIdx.x * 32;
    const int part = blockIdx.y;
    const float* X = part ? key : query;
    float* out = part ? g_kp : g_qp;
    const int woff = part * 128;

    unsigned long long acc2[4][2];
    if (part == 0) {
        float4 bv = *reinterpret_cast<const float4*>(b1 + tx * 4);
        unsigned long long b01 = f32x2_pack(bv.x, bv.y);
        unsigned long long b23 = f32x2_pack(bv.z, bv.w);
        #pragma unroll
        for (int i = 0; i < 4; i++) { acc2[i][0] = b01; acc2[i][1] = b23; }
    } else {
        #pragma unroll
        for (int i = 0; i < 4; i++) { acc2[i][0] = 0ULL; acc2[i][1] = 0ULL; }
    }

    const int xr = tid >> 3, xk = (tid & 7) * 4;

    float4 xreg = *reinterpret_cast<const float4*>(X + (size_t)(R0 + xr) * 128 + xk);
    float4 wreg[4];
    #pragma unroll
    for (int j = 0; j < 4; j++) {
        int idx = tid + j * 256;
        int h = idx >> 3, k4 = (idx & 7) * 4;
        wreg[j] = *reinterpret_cast<const float4*>(W1 + (size_t)h * 256 + woff + k4);
    }

    for (int kc = 0; kc < 4; kc++) {
        xs[xr][xk + 0] = xreg.x; xs[xr][xk + 1] = xreg.y;
        xs[xr][xk + 2] = xreg.z; xs[xr][xk + 3] = xreg.w;
        #pragma unroll
        for (int j = 0; j < 4; j++) {
            int idx = tid + j * 256;
            int h = idx >> 3, k4 = (idx & 7) * 4;
            ws[k4 + 0][h] = wreg[j].x; ws[k4 + 1][h] = wreg[j].y;
            ws[k4 + 2][h] = wreg[j].z; ws[k4 + 3][h] = wreg[j].w;
        }
        __syncthreads();

        if (kc < 3) {
            xreg = *reinterpret_cast<const float4*>(
                X + (size_t)(R0 + xr) * 128 + (kc + 1) * 32 + xk);
            #pragma unroll
            for (int j = 0; j < 4; j++) {
                int idx = tid + j * 256;
                int h = idx >> 3, k4 = (idx & 7) * 4;
                wreg[j] = *reinterpret_cast<const float4*>(
                    W1 + (size_t)h * 256 + woff + (kc + 1) * 32 + k4);
            }
        }

        #pragma unroll 8
        for (int k = 0; k < 32; k++) {
            ulonglong2 wv2 = *reinterpret_cast<const ulonglong2*>(&ws[k][tx * 4]);
            #pragma unroll
            for (int i = 0; i < 4; i++) {
                float xv = xs[ty + 8 * i][k];
                unsigned long long xx = f32x2_pack(xv, xv);
                acc2[i][0] = f32x2_fma(wv2.x, xx, acc2[i][0]);
                acc2[i][1] = f32x2_fma(wv2.y, xx, acc2[i][1]);
            }
        }
        __syncthreads();
    }

    float4 accf[4];
    #pragma unroll
    for (int i = 0; i < 4; i++) {
        f32x2_unpack(acc2[i][0], accf[i].x, accf[i].y);
        f32x2_unpack(acc2[i][1], accf[i].z, accf[i].w);
        int r = R0 + ty + 8 * i;
        *reinterpret_cast<float4*>(out + (size_t)r * 128 + tx * 4) = accf[i];
    }

    float4 w2v = *reinterpret_cast<const float4*>(W2 + tx * 4);
    #pragma unroll
    for (int i = 0; i < 4; i++) {
        float ps = accf[i].x * w2v.x + accf[i].y * w2v.y
                 + accf[i].z * w2v.z + accf[i].w * w2v.w;
        #pragma unroll
        for (int off = 16; off >= 1; off >>= 1)
            ps += __shfl_xor_sync(0xffffffffu, ps, off);
        if (tx == 0) {
            int r = R0 + ty + 8 * i;
            if (part == 0) {
                g_a[r] = 0.5f * ps + b2[0];
            } else {
                g_c[r] = k_mask[r] ? 0.5f * ps : -1e30f;
            }
        }
    }
}

// ================= Kernel 2: fused scoring + exp + value accum (compacted) ===
// s[b,s,t] = a_s + c_t + sum_h 0.5*W2_h*|qp_h + kp_h|   (relu identity)
// grid (S1/64, TSPLIT, B), block 256; tz block handles chunks c = tz, tz+8, ...
__global__ __launch_bounds__(256, 2) void attn_kernel(
    const float* __restrict__ value, const float* __restrict__ W2)
{
    __shared__ float kp_s[32 * 128];    // permuted: chunk (hc, ib) at slot ib*8+hc
    __shared__ float v_s [32 * 128];
    __shared__ float c_s [32];
    __shared__ int   s_ids[64];

    const int tid = threadIdx.x;
    const int warp = tid >> 5, lane = tid & 31;
    const int s_local = lane >> 3, hc = lane & 7;
    const int stile = blockIdx.x, tz = blockIdx.y, b = blockIdx.z;

    const int ns = g_ns[b], nt = g_nt[b];
    if (stile * 64 >= ns) return;

    if (tid < 64) s_ids[tid] = g_slist[b * S1_ + stile * 64 + tid];
    __syncthreads();

    const int iiA = warp * 8 + s_local;
    const bool vA = stile * 64 + iiA < ns;
    const bool vB = stile * 64 + iiA + 4 < ns;
    const int sA = s_ids[iiA];
    const int sB = s_ids[iiA + 4];
    const int rowA = b * S1_ + sA;
    const int rowB = b * S1_ + sB;

    unsigned long long qpA2[8], qpB2[8], w2p[8];
    {
        const float4* qrowA = reinterpret_cast<const float4*>(
            g_qp + (size_t)rowA * HID_ + hc * 16);
        const float4* qrowB = reinterpret_cast<const float4*>(
            g_qp + (size_t)rowB * HID_ + hc * 16);
        #pragma unroll
        for (int i = 0; i < 4; i++) {
            float4 qa = qrowA[i];
            qpA2[2 * i]     = f32x2_pack(qa.x, qa.y);
            qpA2[2 * i + 1] = f32x2_pack(qa.z, qa.w);
            float4 qb = qrowB[i];
            qpB2[2 * i]     = f32x2_pack(qb.x, qb.y);
            qpB2[2 * i + 1] = f32x2_pack(qb.z, qb.w);
            float4 w = *reinterpret_cast<const float4*>(W2 + hc * 16 + i * 4);
            w2p[2 * i]     = f32x2_pack(0.5f * w.x, 0.5f * w.y);
            w2p[2 * i + 1] = f32x2_pack(0.5f * w.z, 0.5f * w.w);
        }
    }
    const float aA = g_a[rowA];
    const float aB = g_a[rowB];

    unsigned long long vaccA[8], vaccB[8];
    #pragma unroll
    for (int i = 0; i < 8; i++) { vaccA[i] = 0ULL; vaccB[i] = 0ULL; }
    float denA = 0.f, denB = 0.f;

    const unsigned long long ABS2 = 0x7FFFFFFF7FFFFFFFULL;
    const int bit0 = hc & 1, bit1 = (hc >> 1) & 1, bit2 = (hc >> 2) & 1;
    const int bcast = lane & 24;
    const int* tlist = g_tlist + b * S2_;

    for (int c = tz; c * 32 < nt; c += TSPLIT) {
        const int jb = c * 32;
        __syncthreads();
        #pragma unroll
        for (int j = 0; j < 4; j++) {
            int idx = tid + j * 256;            // 0..1023 float4s
            int tt = idx >> 5, l = idx & 31;
            int t = tlist[jb + tt];             // padded with 0 beyond nt
            int h4 = ((l & 7) << 2) | (l >> 3); // inverse of slot permutation
            const float4* krow = reinterpret_cast<const float4*>(
                g_kp + (size_t)(b * S2_ + t) * HID_);
            const float4* vrow = reinterpret_cast<const float4*>(
                value + (size_t)(b * S2_ + t) * HD_);
            reinterpret_cast<float4*>(kp_s)[tt * 32 + l] = krow[h4];
            reinterpret_cast<float4*>(v_s )[tt * 32 + l] = vrow[h4];
        }
        if (tid < 32) {
            int j = jb + tid;
            c_s[tid] = (j < nt) ? g_c[b * S2_ + tlist[j]] : -1e30f;
        }
        __syncthreads();

        #pragma unroll 1
        for (int g = 0; g < 4; g++) {
            float rA[4], rB[4];
            #pragma unroll
            for (int k = 0; k < 4; k++) {
                float m0A, m0B, m1A, m1B;
                #pragma unroll
                for (int half = 0; half < 2; half++) {
                    const float* kprow = kp_s + (g * 8 + 2 * k + half) * 128;
                    unsigned long long a0 = 0ULL, a1 = 0ULL, b0 = 0ULL, b1 = 0ULL;
                    #pragma unroll
                    for (int ib = 0; ib < 4; ib++) {
                        ulonglong2 kv = *reinterpret_cast<const ulonglong2*>(
                            kprow + ib * 32 + hc * 4);
                        unsigned long long xA01 = f32x2_add(qpA2[2 * ib],     kv.x) & ABS2;
                        unsigned long long xA23 = f32x2_add(qpA2[2 * ib + 1], kv.y) & ABS2;
                        unsigned long long xB01 = f32x2_add(qpB2[2 * ib],     kv.x) & ABS2;
                        unsigned long long xB23 = f32x2_add(qpB2[2 * ib + 1], kv.y) & ABS2;
                        a0 = f32x2_fma(xA01, w2p[2 * ib],     a0);
                        a1 = f32x2_fma(xA23, w2p[2 * ib + 1], a1);
                        b0 = f32x2_fma(xB01, w2p[2 * ib],     b0);
                        b1 = f32x2_fma(xB23, w2p[2 * ib + 1], b1);
                    }
                    float la, ha, lb, hb;
                    f32x2_unpack(f32x2_add(a0, a1), la, ha);
                    f32x2_unpack(f32x2_add(b0, b1), lb, hb);
                    if (half == 0) { m0A = la + ha; m0B = lb + hb; }
                    else           { m1A = la + ha; m1B = lb + hb; }
                }
                rA[k] = bfly_step(bit0 ? m1A : m0A, bit0 ? m0A : m1A, 1);
                rB[k] = bfly_step(bit0 ? m1B : m0B, bit0 ? m0B : m1B, 1);
            }
            float sA2[2], sB2[2];
            #pragma unroll
            for (int k = 0; k < 2; k++) {
                sA2[k] = bfly_step(bit1 ? rA[2 * k + 1] : rA[2 * k],
                                   bit1 ? rA[2 * k] : rA[2 * k + 1], 2);
                sB2[k] = bfly_step(bit1 ? rB[2 * k + 1] : rB[2 * k],
                                   bit1 ? rB[2 * k] : rB[2 * k + 1], 2);
            }
            float scA = bfly_step(bit2 ? sA2[1] : sA2[0],
                                  bit2 ? sA2[0] : sA2[1], 4);
            float scB = bfly_step(bit2 ? sB2[1] : sB2[0],
                                  bit2 ? sB2[0] : sB2[1], 4);

            float ct = c_s[g * 8 + hc];
            float pA = __expf(scA + aA + ct);   // ct = -1e30 on padding => p = 0
            float pB = __expf(scB + aB + ct);
            denA += pA;
            denB += pB;

            #pragma unroll
            for (int j = 0; j < 8; j++) {
                float pAj = __shfl_sync(0xffffffffu, pA, bcast + j);
                float pBj = __shfl_sync(0xffffffffu, pB, bcast + j);
                unsigned long long pA2 = f32x2_pack(pAj, pAj);
                unsigned long long pB2 = f32x2_pack(pBj, pBj);
                const float* vrow2 = v_s + (g * 8 + j) * 128;
                #pragma unroll
                for (int m = 0; m < 4; m++) {
                    ulonglong2 vv = *reinterpret_cast<const ulonglong2*>(
                        vrow2 + m * 32 + hc * 4);
                    vaccA[2 * m]     = f32x2_fma(vv.x, pA2, vaccA[2 * m]);
                    vaccA[2 * m + 1] = f32x2_fma(vv.y, pA2, vaccA[2 * m + 1]);
                    vaccB[2 * m]     = f32x2_fma(vv.x, pB2, vaccB[2 * m]);
                    vaccB[2 * m + 1] = f32x2_fma(vv.y, pB2, vaccB[2 * m + 1]);
                }
            }
        }
    }

    #pragma unroll
    for (int off = 1; off <= 4; off <<= 1) {
        denA += __shfl_xor_sync(0xffffffffu, denA, off);
        denB += __shfl_xor_sync(0xffffffffu, denB, off);
    }

    // row-major partial layout: [row][k][d] / [row][k]
    if (vA) {
        float* outA = g_pout + ((size_t)rowA * TSPLIT + tz) * HD_ + hc * 16;
        #pragma unroll
        for (int m = 0; m < 4; m++) {
            float x0, x1, x2, x3;
            f32x2_unpack(vaccA[2 * m],     x0, x1);
            f32x2_unpack(vaccA[2 * m + 1], x2, x3);
            *reinterpret_cast<float4*>(outA + m * 4) = make_float4(x0, x1, x2, x3);
        }
        if (hc == 0) g_pden[(size_t)rowA * TSPLIT + tz] = denA;
    }
    if (vB) {
        float* outB = g_pout + ((size_t)rowB * TSPLIT + tz) * HD_ + hc * 16;
        #pragma unroll
        for (int m = 0; m < 4; m++) {
            float x0, x1, x2, x3;
            f32x2_unpack(vaccB[2 * m],     x0, x1);
            f32x2_unpack(vaccB[2 * m + 1], x2, x3);
            *reinterpret_cast<float4*>(outB + m * 4) = make_float4(x0, x1, x2, x3);
        }
        if (hc == 0) g_pden[(size_t)rowB * TSPLIT + tz] = denB;
    }
}

// ================= Kernel 3: reduce partials + normalize + q_mask ============
__global__ __launch_bounds__(256) void reduce_kernel(
    const int* __restrict__ q_mask, float* __restrict__ out)
{
    int idx = blockIdx.x * 256 + threadIdx.x;   // float4 index
    if (idx >= B_ * S1_ * (HD_ / 4)) return;
    int d4 = idx & 31;
    int row = idx >> 5;                          // b*S1 + s
    if (q_mask[row] == 0) {                      // masked row: exact zero output
        reinterpret_cast<float4*>(out)[idx] = make_float4(0.f, 0.f, 0.f, 0.f);
        return;
    }
    float4 sum = make_float4(0.f, 0.f, 0.f, 0.f);
    #pragma unroll
    for (int k = 0; k < TSPLIT; k++) {
        float4 p = reinterpret_cast<const float4*>(g_pout)
                       [((size_t)row * TSPLIT + k) * 32 + d4];
        sum.x += p.x; sum.y += p.y; sum.z += p.z; sum.w += p.w;
    }
    float4 e0 = reinterpret_cast<const float4*>(g_pden)[row * 2];
    float4 e1 = reinterpret_cast<const float4*>(g_pden)[row * 2 + 1];
    float dsum = (e0.x + e0.y) + (e0.z + e0.w) + (e1.x + e1.y) + (e1.z + e1.w);
    float scale = 1.0f / fmaxf(dsum, 2e-15f);
    reinterpret_cast<float4*>(out)[idx] =
        make_float4(sum.x * scale, sum.y * scale, sum.z * scale, sum.w * scale);
}

// ================= launch ====================================================
extern "C" void kernel_launch(void* const* d_in, const int* in_sizes, int n_in,
                              void* d_out, int out_size)
{
    const float* query  = (const float*)d_in[0];
    const float* key    = (const float*)d_in[1];
    const float* value  = (const float*)d_in[2];
    const int*   q_mask = (const int*)  d_in[3];
    const int*   k_mask = (const int*)  d_in[4];
    const float* W1     = (const float*)d_in[5];
    const float* b1     = (const float*)d_in[6];
    const float* W2     = (const float*)d_in[7];
    const float* b2     = (const float*)d_in[8];
    float* out = (float*)d_out;

    compact_kernel<<<B_, 512>>>(q_mask, k_mask);
    proj_kernel  <<<dim3(128, 2), 256>>>(query, key, W1, b1, W2, b2, k_mask);
    attn_kernel  <<<dim3(S1_ / 64, TSPLIT, B_), 256>>>(value, W2);
    reduce_kernel<<<(B_ * S1_ * (HD_ / 4) + 255) / 256, 256>>>(q_mask, out);
}

// round 17
// speedup vs baseline: 1.6000x; 1.0375x over previous
#include <cuda_runtime.h>
#include <cuda_bf16.h>

// Problem constants
#define B_   8
#define S1_  512
#define S2_  512
#define HID_ 128
#define HD_  128
#define TSPLIT 8

// ---------------- scratch (static device memory; no allocations) -------------
__device__ float g_qp  [B_ * S1_ * HID_];                 // 2 MB
__device__ float g_kp  [B_ * S2_ * HID_];                 // 2 MB
__device__ float g_a   [B_ * S1_];                        // 0.5*qp.W2 + b2
__device__ float g_c   [B_ * S2_];                        // 0.5*kp.W2 (or -1e30 if masked)
__device__ int   g_slist[B_ * S1_];                       // compacted active s ids
__device__ int   g_tlist[B_ * S2_];                       // compacted active t ids
__device__ int   g_ns[B_], g_nt[B_];
__device__ float g_pout[B_ * S1_ * TSPLIT * HD_];         // [row][k][d] partials
__device__ float g_pden[B_ * S1_ * TSPLIT];               // [row][k] partials

// ---------------- packed f32x2 helpers (Blackwell-only PTX) ------------------
__device__ __forceinline__ unsigned long long f32x2_add(unsigned long long a,
                                                        unsigned long long b) {
    unsigned long long r;
    asm("add.rn.f32x2 %0, %1, %2;" : "=l"(r) : "l"(a), "l"(b));
    return r;
}
__device__ __forceinline__ unsigned long long f32x2_fma(unsigned long long a,
                                                        unsigned long long b,
                                                        unsigned long long c) {
    unsigned long long r;
    asm("fma.rn.f32x2 %0, %1, %2, %3;" : "=l"(r) : "l"(a), "l"(b), "l"(c));
    return r;
}
__device__ __forceinline__ unsigned long long f32x2_pack(float lo, float hi) {
    unsigned long long r;
    asm("mov.b64 %0, {%1, %2};" : "=l"(r) : "f"(lo), "f"(hi));
    return r;
}
__device__ __forceinline__ void f32x2_unpack(unsigned long long a, float& lo, float& hi) {
    asm("mov.b64 {%0, %1}, %2;" : "=f"(lo), "=f"(hi) : "l"(a));
}
__device__ __forceinline__ float bfly_step(float keep, float send, int off) {
    return keep + __shfl_xor_sync(0xffffffffu, send, off);
}

// ================= Kernel 0: compact active s / t index lists ================
// One block per batch, 512 threads. Deterministic ballot+scan compaction.
__global__ __launch_bounds__(512) void compact_kernel(
    const int* __restrict__ q_mask, const int* __restrict__ k_mask)
{
    __shared__ int wcnt[16], woff[16];
    __shared__ int total_sh;
    const int b = blockIdx.x, tid = threadIdx.x;
    const int lane = tid & 31, wid = tid >> 5;

    // ---- t side (k_mask) ----
    int m = k_mask[b * S2_ + tid] != 0;
    unsigned bal = __ballot_sync(0xffffffffu, m);
    if (lane == 0) wcnt[wid] = __popc(bal);
    __syncthreads();
    if (tid == 0) {
        int acc = 0;
        for (int i = 0; i < 16; i++) { woff[i] = acc; acc += wcnt[i]; }
        total_sh = acc;
    }
    __syncthreads();
    int pos = woff[wid] + __popc(bal & ((1u << lane) - 1));
    if (m) g_tlist[b * S2_ + pos] = tid;
    int ntv = total_sh;
    if (tid == 0) g_nt[b] = ntv;
    for (int j = ntv + tid; j < S2_; j += 512) g_tlist[b * S2_ + j] = 0;
    __syncthreads();

    // ---- s side (q_mask) ----
    m = q_mask[b * S1_ + tid] != 0;
    bal = __ballot_sync(0xffffffffu, m);
    if (lane == 0) wcnt[wid] = __popc(bal);
    __syncthreads();
    if (tid == 0) {
        int acc = 0;
        for (int i = 0; i < 16; i++) { woff[i] = acc; acc += wcnt[i]; }
        total_sh = acc;
    }
    __syncthreads();
    pos = woff[wid] + __popc(bal & ((1u << lane) - 1));
    if (m) g_slist[b * S1_ + pos] = tid;
    int nsv = total_sh;
    if (tid == 0) g_ns[b] = nsv;
    for (int j = nsv + tid; j < S1_; j += 512) g_slist[b * S1_ + j] = 0;
}

// ================= Kernel 1: projections qp / kp + linear score terms ========
// grid (128, 2), block 256. ALL rows. 32-row tiles, register double-buffered.
// xs rows padded to 36 floats so the inner loop reads xs via LDS.128.
__global__ __launch_bounds__(256) void proj_kernel(
    const float* __restrict__ query, const float* __restrict__ key,
    const float* __restrict__ W1, const float* __restrict__ b1,
    const float* __restrict__ W2, const float* __restrict__ b2,
    const int* __restrict__ k_mask)
{
    __shared__ float xs[32][36];    // 144B row stride (16B multiple)
    __shared__ float ws[32][132];

    const int tid = threadIdx.x;
    const int tx = tid & 31;
    const int ty = tid >> 5;
    const int R0 = blockIdx.x * 32;
    const int part = blockIdx.y;
    const float* X = part ? key : query;
    float* out = part ? g_kp : g_qp;
    const int woff = part * 128;

    unsigned long long acc2[4][2];
    if (part == 0) {
        float4 bv = *reinterpret_cast<const float4*>(b1 + tx * 4);
        unsigned long long b01 = f32x2_pack(bv.x, bv.y);
        unsigned long long b23 = f32x2_pack(bv.z, bv.w);
        #pragma unroll
        for (int i = 0; i < 4; i++) { acc2[i][0] = b01; acc2[i][1] = b23; }
    } else {
        #pragma unroll
        for (int i = 0; i < 4; i++) { acc2[i][0] = 0ULL; acc2[i][1] = 0ULL; }
    }

    const int xr = tid >> 3, xk = (tid & 7) * 4;

    float4 xreg = *reinterpret_cast<const float4*>(X + (size_t)(R0 + xr) * 128 + xk);
    float4 wreg[4];
    #pragma unroll
    for (int j = 0; j < 4; j++) {
        int idx = tid + j * 256;
        int h = idx >> 3, k4 = (idx & 7) * 4;
        wreg[j] = *reinterpret_cast<const float4*>(W1 + (size_t)h * 256 + woff + k4);
    }

    for (int kc = 0; kc < 4; kc++) {
        *reinterpret_cast<float4*>(&xs[xr][xk]) = xreg;
        #pragma unroll
        for (int j = 0; j < 4; j++) {
            int idx = tid + j * 256;
            int h = idx >> 3, k4 = (idx & 7) * 4;
            ws[k4 + 0][h] = wreg[j].x; ws[k4 + 1][h] = wreg[j].y;
            ws[k4 + 2][h] = wreg[j].z; ws[k4 + 3][h] = wreg[j].w;
        }
        __syncthreads();

        if (kc < 3) {
            xreg = *reinterpret_cast<const float4*>(
                X + (size_t)(R0 + xr) * 128 + (kc + 1) * 32 + xk);
            #pragma unroll
            for (int j = 0; j < 4; j++) {
                int idx = tid + j * 256;
                int h = idx >> 3, k4 = (idx & 7) * 4;
                wreg[j] = *reinterpret_cast<const float4*>(
                    W1 + (size_t)h * 256 + woff + (kc + 1) * 32 + k4);
            }
        }

        #pragma unroll
        for (int k4 = 0; k4 < 32; k4 += 4) {
            float4 xv4[4];
            #pragma unroll
            for (int i = 0; i < 4; i++)
                xv4[i] = *reinterpret_cast<const float4*>(&xs[ty + 8 * i][k4]);
            #pragma unroll
            for (int kk = 0; kk < 4; kk++) {
                ulonglong2 wv2 = *reinterpret_cast<const ulonglong2*>(
                    &ws[k4 + kk][tx * 4]);
                #pragma unroll
                for (int i = 0; i < 4; i++) {
                    float xv = (kk == 0) ? xv4[i].x : (kk == 1) ? xv4[i].y
                             : (kk == 2) ? xv4[i].z : xv4[i].w;
                    unsigned long long xx = f32x2_pack(xv, xv);
                    acc2[i][0] = f32x2_fma(wv2.x, xx, acc2[i][0]);
                    acc2[i][1] = f32x2_fma(wv2.y, xx, acc2[i][1]);
                }
            }
        }
        __syncthreads();
    }

    float4 accf[4];
    #pragma unroll
    for (int i = 0; i < 4; i++) {
        f32x2_unpack(acc2[i][0], accf[i].x, accf[i].y);
        f32x2_unpack(acc2[i][1], accf[i].z, accf[i].w);
        int r = R0 + ty + 8 * i;
        *reinterpret_cast<float4*>(out + (size_t)r * 128 + tx * 4) = accf[i];
    }

    float4 w2v = *reinterpret_cast<const float4*>(W2 + tx * 4);
    #pragma unroll
    for (int i = 0; i < 4; i++) {
        float ps = accf[i].x * w2v.x + accf[i].y * w2v.y
                 + accf[i].z * w2v.z + accf[i].w * w2v.w;
        #pragma unroll
        for (int off = 16; off >= 1; off >>= 1)
            ps += __shfl_xor_sync(0xffffffffu, ps, off);
        if (tx == 0) {
            int r = R0 + ty + 8 * i;
            if (part == 0) {
                g_a[r] = 0.5f * ps + b2[0];
            } else {
                g_c[r] = k_mask[r] ? 0.5f * ps : -1e30f;
            }
        }
    }
}

// ================= Kernel 2: fused scoring + exp + value accum (compacted) ===
// s[b,s,t] = a_s + c_t + sum_h 0.5*W2_h*|qp_h + kp_h|   (relu identity)
// grid (S1/64, TSPLIT, B), block 256; tz block handles chunks c = tz, tz+8, ...
__global__ __launch_bounds__(256, 2) void attn_kernel(
    const float* __restrict__ value, const float* __restrict__ W2)
{
    __shared__ float kp_s[32 * 128];    // permuted: chunk (hc, ib) at slot ib*8+hc
    __shared__ float v_s [32 * 128];
    __shared__ float c_s [32];
    __shared__ int   s_ids[64];

    const int tid = threadIdx.x;
    const int warp = tid >> 5, lane = tid & 31;
    const int s_local = lane >> 3, hc = lane & 7;
    const int stile = blockIdx.x, tz = blockIdx.y, b = blockIdx.z;

    const int ns = g_ns[b], nt = g_nt[b];
    if (stile * 64 >= ns) return;

    if (tid < 64) s_ids[tid] = g_slist[b * S1_ + stile * 64 + tid];
    __syncthreads();

    const int iiA = warp * 8 + s_local;
    const bool vA = stile * 64 + iiA < ns;
    const bool vB = stile * 64 + iiA + 4 < ns;
    const int sA = s_ids[iiA];
    const int sB = s_ids[iiA + 4];
    const int rowA = b * S1_ + sA;
    const int rowB = b * S1_ + sB;

    unsigned long long qpA2[8], qpB2[8], w2p[8];
    {
        const float4* qrowA = reinterpret_cast<const float4*>(
            g_qp + (size_t)rowA * HID_ + hc * 16);
        const float4* qrowB = reinterpret_cast<const float4*>(
            g_qp + (size_t)rowB * HID_ + hc * 16);
        #pragma unroll
        for (int i = 0; i < 4; i++) {
            float4 qa = qrowA[i];
            qpA2[2 * i]     = f32x2_pack(qa.x, qa.y);
            qpA2[2 * i + 1] = f32x2_pack(qa.z, qa.w);
            float4 qb = qrowB[i];
            qpB2[2 * i]     = f32x2_pack(qb.x, qb.y);
            qpB2[2 * i + 1] = f32x2_pack(qb.z, qb.w);
            float4 w = *reinterpret_cast<const float4*>(W2 + hc * 16 + i * 4);
            w2p[2 * i]     = f32x2_pack(0.5f * w.x, 0.5f * w.y);
            w2p[2 * i + 1] = f32x2_pack(0.5f * w.z, 0.5f * w.w);
        }
    }
    const float aA = g_a[rowA];
    const float aB = g_a[rowB];

    unsigned long long vaccA[8], vaccB[8];
    #pragma unroll
    for (int i = 0; i < 8; i++) { vaccA[i] = 0ULL; vaccB[i] = 0ULL; }
    float denA = 0.f, denB = 0.f;

    const unsigned long long ABS2 = 0x7FFFFFFF7FFFFFFFULL;
    const int bit0 = hc & 1, bit1 = (hc >> 1) & 1, bit2 = (hc >> 2) & 1;
    const int bcast = lane & 24;
    const int* tlist = g_tlist + b * S2_;

    for (int c = tz; c * 32 < nt; c += TSPLIT) {
        const int jb = c * 32;
        __syncthreads();
        #pragma unroll
        for (int j = 0; j < 4; j++) {
            int idx = tid + j * 256;            // 0..1023 float4s
            int tt = idx >> 5, l = idx & 31;
            int t = tlist[jb + tt];             // padded with 0 beyond nt
            int h4 = ((l & 7) << 2) | (l >> 3); // inverse of slot permutation
            const float4* krow = reinterpret_cast<const float4*>(
                g_kp + (size_t)(b * S2_ + t) * HID_);
            const float4* vrow = reinterpret_cast<const float4*>(
                value + (size_t)(b * S2_ + t) * HD_);
            reinterpret_cast<float4*>(kp_s)[tt * 32 + l] = krow[h4];
            reinterpret_cast<float4*>(v_s )[tt * 32 + l] = vrow[h4];
        }
        if (tid < 32) {
            int j = jb + tid;
            c_s[tid] = (j < nt) ? g_c[b * S2_ + tlist[j]] : -1e30f;
        }
        __syncthreads();

        #pragma unroll 1
        for (int g = 0; g < 4; g++) {
            float rA[4], rB[4];
            #pragma unroll
            for (int k = 0; k < 4; k++) {
                float m0A, m0B, m1A, m1B;
                #pragma unroll
                for (int half = 0; half < 2; half++) {
                    const float* kprow = kp_s + (g * 8 + 2 * k + half) * 128;
                    unsigned long long a0 = 0ULL, a1 = 0ULL, b0 = 0ULL, b1 = 0ULL;
                    #pragma unroll
                    for (int ib = 0; ib < 4; ib++) {
                        ulonglong2 kv = *reinterpret_cast<const ulonglong2*>(
                            kprow + ib * 32 + hc * 4);
                        unsigned long long xA01 = f32x2_add(qpA2[2 * ib],     kv.x) & ABS2;
                        unsigned long long xA23 = f32x2_add(qpA2[2 * ib + 1], kv.y) & ABS2;
                        unsigned long long xB01 = f32x2_add(qpB2[2 * ib],     kv.x) & ABS2;
                        unsigned long long xB23 = f32x2_add(qpB2[2 * ib + 1], kv.y) & ABS2;
                        a0 = f32x2_fma(xA01, w2p[2 * ib],     a0);
                        a1 = f32x2_fma(xA23, w2p[2 * ib + 1], a1);
                        b0 = f32x2_fma(xB01, w2p[2 * ib],     b0);
                        b1 = f32x2_fma(xB23, w2p[2 * ib + 1], b1);
                    }
                    float la, ha, lb, hb;
                    f32x2_unpack(f32x2_add(a0, a1), la, ha);
                    f32x2_unpack(f32x2_add(b0, b1), lb, hb);
                    if (half == 0) { m0A = la + ha; m0B = lb + hb; }
                    else           { m1A = la + ha; m1B = lb + hb; }
                }
                rA[k] = bfly_step(bit0 ? m1A : m0A, bit0 ? m0A : m1A, 1);
                rB[k] = bfly_step(bit0 ? m1B : m0B, bit0 ? m0B : m1B, 1);
            }
            float sA2[2], sB2[2];
            #pragma unroll
            for (int k = 0; k < 2; k++) {
                sA2[k] = bfly_step(bit1 ? rA[2 * k + 1] : rA[2 * k],
                                   bit1 ? rA[2 * k] : rA[2 * k + 1], 2);
                sB2[k] = bfly_step(bit1 ? rB[2 * k + 1] : rB[2 * k],
                                   bit1 ? rB[2 * k] : rB[2 * k + 1], 2);
            }
            float scA = bfly_step(bit2 ? sA2[1] : sA2[0],
                                  bit2 ? sA2[0] : sA2[1], 4);
            float scB = bfly_step(bit2 ? sB2[1] : sB2[0],
                                  bit2 ? sB2[0] : sB2[1], 4);

            float ct = c_s[g * 8 + hc];
            float pA = __expf(scA + aA + ct);   // ct = -1e30 on padding => p = 0
            float pB = __expf(scB + aB + ct);
            denA += pA;
            denB += pB;

            #pragma unroll
            for (int j = 0; j < 8; j++) {
                float pAj = __shfl_sync(0xffffffffu, pA, bcast + j);
                float pBj = __shfl_sync(0xffffffffu, pB, bcast + j);
                unsigned long long pA2 = f32x2_pack(pAj, pAj);
                unsigned long long pB2 = f32x2_pack(pBj, pBj);
                const float* vrow2 = v_s + (g * 8 + j) * 128;
                #pragma unroll
                for (int m = 0; m < 4; m++) {
                    ulonglong2 vv = *reinterpret_cast<const ulonglong2*>(
                        vrow2 + m * 32 + hc * 4);
                    vaccA[2 * m]     = f32x2_fma(vv.x, pA2, vaccA[2 * m]);
                    vaccA[2 * m + 1] = f32x2_fma(vv.y, pA2, vaccA[2 * m + 1]);
                    vaccB[2 * m]     = f32x2_fma(vv.x, pB2, vaccB[2 * m]);
                    vaccB[2 * m + 1] = f32x2_fma(vv.y, pB2, vaccB[2 * m + 1]);
                }
            }
        }
    }

    #pragma unroll
    for (int off = 1; off <= 4; off <<= 1) {
        denA += __shfl_xor_sync(0xffffffffu, denA, off);
        denB += __shfl_xor_sync(0xffffffffu, denB, off);
    }

    // row-major partial layout: [row][k][d] / [row][k]
    if (vA) {
        float* outA = g_pout + ((size_t)rowA * TSPLIT + tz) * HD_ + hc * 16;
        #pragma unroll
        for (int m = 0; m < 4; m++) {
            float x0, x1, x2, x3;
            f32x2_unpack(vaccA[2 * m],     x0, x1);
            f32x2_unpack(vaccA[2 * m + 1], x2, x3);
            *reinterpret_cast<float4*>(outA + m * 4) = make_float4(x0, x1, x2, x3);
        }
        if (hc == 0) g_pden[(size_t)rowA * TSPLIT + tz] = denA;
    }
    if (vB) {
        float* outB = g_pout + ((size_t)rowB * TSPLIT + tz) * HD_ + hc * 16;
        #pragma unroll
        for (int m = 0; m < 4; m++) {
            float x0, x1, x2, x3;
            f32x2_unpack(vaccB[2 * m],     x0, x1);
            f32x2_unpack(vaccB[2 * m + 1], x2, x3);
            *reinterpret_cast<float4*>(outB + m * 4) = make_float4(x0, x1, x2, x3);
        }
        if (hc == 0) g_pden[(size_t)rowB * TSPLIT + tz] = denB;
    }
}

// ================= Kernel 3: reduce partials + normalize + q_mask ============
// 2 outputs per thread (same row: d4 and d4+16) -> pden amortized, 2x MLP.
__global__ __launch_bounds__(256) void reduce_kernel(
    const int* __restrict__ q_mask, float* __restrict__ out)
{
    int t2 = blockIdx.x * 256 + threadIdx.x;     // 0 .. 65535
    if (t2 >= B_ * S1_ * 16) return;
    int d4 = t2 & 15;
    int row = t2 >> 4;                           // b*S1 + s
    float4* outv = reinterpret_cast<float4*>(out) + (size_t)row * 32 + d4;
    if (q_mask[row] == 0) {                      // masked row: exact zero output
        outv[0]  = make_float4(0.f, 0.f, 0.f, 0.f);
        outv[16] = make_float4(0.f, 0.f, 0.f, 0.f);
        return;
    }
    float4 sum0 = make_float4(0.f, 0.f, 0.f, 0.f);
    float4 sum1 = make_float4(0.f, 0.f, 0.f, 0.f);
    const float4* pbase = reinterpret_cast<const float4*>(g_pout)
                          + (size_t)row * TSPLIT * 32 + d4;
    #pragma unroll
    for (int k = 0; k < TSPLIT; k++) {
        float4 p0 = pbase[k * 32];
        float4 p1 = pbase[k * 32 + 16];
        sum0.x += p0.x; sum0.y += p0.y; sum0.z += p0.z; sum0.w += p0.w;
        sum1.x += p1.x; sum1.y += p1.y; sum1.z += p1.z; sum1.w += p1.w;
    }
    float4 e0 = reinterpret_cast<const float4*>(g_pden)[row * 2];
    float4 e1 = reinterpret_cast<const float4*>(g_pden)[row * 2 + 1];
    float dsum = (e0.x + e0.y) + (e0.z + e0.w) + (e1.x + e1.y) + (e1.z + e1.w);
    float scale = 1.0f / fmaxf(dsum, 2e-15f);
    outv[0]  = make_float4(sum0.x * scale, sum0.y * scale,
                           sum0.z * scale, sum0.w * scale);
    outv[16] = make_float4(sum1.x * scale, sum1.y * scale,
                           sum1.z * scale, sum1.w * scale);
}

// ================= launch ====================================================
extern "C" void kernel_launch(void* const* d_in, const int* in_sizes, int n_in,
                              void* d_out, int out_size)
{
    const float* query  = (const float*)d_in[0];
    const float* key    = (const float*)d_in[1];
    const float* value  = (const float*)d_in[2];
    const int*   q_mask = (const int*)  d_in[3];
    const int*   k_mask = (const int*)  d_in[4];
    const float* W1     = (const float*)d_in[5];
    const float* b1     = (const float*)d_in[6];
    const float* W2     = (const float*)d_in[7];
    const float* b2     = (const float*)d_in[8];
    float* out = (float*)d_out;

    compact_kernel<<<B_, 512>>>(q_mask, k_mask);
    proj_kernel  <<<dim3(128, 2), 256>>>(query, key, W1, b1, W2, b2, k_mask);
    attn_kernel  <<<dim3(S1_ / 64, TSPLIT, B_), 256>>>(value, W2);
    reduce_kernel<<<(B_ * S1_ * 16 + 255) / 256, 256>>>(q_mask, out);
}